// round 5
// baseline (speedup 1.0000x reference)
#include <cuda_runtime.h>
#include <math.h>
#include <stdint.h>

// Problem constants
#define Nn   4096
#define KK   8
#define FD   512
#define NFW  532          // 512 + 4 + 16
#define EAW  1029         // 5 + 2*512
#define NKE  (Nn*KK)      // 32768
#define EATOT ((unsigned)NKE * EAW)   // 33,718,272 floats

// Output layout (flattened float32 concat of the tuple)
#define NF_OFF   ((size_t)0)
#define EI_OFF   ((size_t)Nn*NFW)                 // 2179072
#define EA_OFF   (EI_OFF + (size_t)2*NKE)         // 2244608
#define OCC_OFF  (EA_OFF + (size_t)NKE*EAW)       // 35962880
#define MASK_OFF (OCC_OFF + (size_t)Nn)           // 35966976

#define DIST_T   108.0f
#define DIST_T2  11666.0f
#define SENT_D   1e30f
#define SENT_I   0x7fffffff

__device__ float2 g_em  [NKE];      // (mask, dst-as-int-bits)
__device__ float  g_head[NKE * 5];  // per-edge scalar features (pre-masked)

// ---------------------------------------------------------------------------
// K1 (fused): reid norm + pos_normed + KNN + topology + occ + per-edge
// scalars. 512 blocks x 256 threads; one warp per node row.
// ---------------------------------------------------------------------------
__global__ void __launch_bounds__(256)
k_graph(const float* __restrict__ reid, const float* __restrict__ pos,
        float* __restrict__ out)
{
    __shared__ float2 sc[Nn];          // all centers (32 KB)
    int tid = threadIdx.x;
    int warp = tid >> 5, lane = tid & 31;
    int i = blockIdx.x * 8 + warp;     // this warp's node row

    // build centers from pos directly (no cross-block dependency)
    for (int j = tid; j < Nn; j += 256) {
        float4 p = ((const float4*)pos)[j];
        sc[j] = make_float2(0.5f*(p.x + p.z), 0.5f*(p.y + p.w));
    }

    // ---- reid L2 norm (independent of sc) ----
    {
        const float4* r = (const float4*)(reid + (size_t)i * FD);
        float4 v[4];
        float s = 0.0f;
#pragma unroll
        for (int u = 0; u < 4; u++) {
            v[u] = r[lane + 32*u];
            s += v[u].x*v[u].x + v[u].y*v[u].y + v[u].z*v[u].z + v[u].w*v[u].w;
        }
#pragma unroll
        for (int o = 16; o > 0; o >>= 1) s += __shfl_xor_sync(0xffffffffu, s, o);
        float inv = 1.0f / (sqrtf(s) + 1e-12f);
        float4* o4 = (float4*)(out + (size_t)i * NFW);
#pragma unroll
        for (int u = 0; u < 4; u++) {
            float4 w = v[u];
            w.x *= inv; w.y *= inv; w.z *= inv; w.w *= inv;
            o4[lane + 32*u] = w;
        }
        if (lane == 0) {
            float4 p = ((const float4*)pos)[i];
            float cx = 0.5f*(p.x+p.z), cy = 0.5f*(p.y+p.w);
            float w = p.z - p.x, h = p.w - p.y;
            float* o = out + (size_t)i * NFW;
            o[512] = cx / 1920.0f;
            o[513] = cy / 1080.0f;
            o[514] = w  / 1920.0f;
            o[515] = h  / 1080.0f;
        }
    }
    __syncthreads();

    // ---- KNN scan ----
    float2 ci = sc[i];
    float dist[KK]; int idx[KK];
#pragma unroll
    for (int u = 0; u < KK; u++) { dist[u] = SENT_D; idx[u] = SENT_I; }

    for (int j = lane; j < Nn; j += 32) {
        float dx = ci.x - sc[j].x;
        float dy = ci.y - sc[j].y;
        float d2 = dx*dx + dy*dy;
        if (j != i && d2 <= DIST_T2) {
            float Dv = sqrtf(fmaxf(d2, 1e-12f));
            if (Dv <= DIST_T) {
                float kd = Dv; int ki = j;
#pragma unroll
                for (int u = 0; u < KK; u++) {
                    bool sw = (kd < dist[u]) || (kd == dist[u] && ki < idx[u]);
                    if (sw) {
                        float td = dist[u]; int ti = idx[u];
                        dist[u] = kd; idx[u] = ki;
                        kd = td; ki = ti;
                    }
                }
            }
        }
    }

    // ---- warp merge: 8 rounds of packed (distBits, idx) min-reduce ----
    float res_d[KK]; int res_i[KK];
#pragma unroll
    for (int k = 0; k < KK; k++) {
        unsigned long long key =
            ((unsigned long long)__float_as_uint(dist[0]) << 32) | (unsigned)idx[0];
#pragma unroll
        for (int o = 16; o > 0; o >>= 1) {
            unsigned long long other = __shfl_xor_sync(0xffffffffu, key, o);
            if (other < key) key = other;
        }
        res_d[k] = __uint_as_float((unsigned)(key >> 32));
        res_i[k] = (int)(unsigned)(key & 0xffffffffull);
        unsigned long long mine =
            ((unsigned long long)__float_as_uint(dist[0]) << 32) | (unsigned)idx[0];
        if (mine == key) {
#pragma unroll
            for (int u = 0; u < KK-1; u++) { dist[u] = dist[u+1]; idx[u] = idx[u+1]; }
            dist[KK-1] = SENT_D; idx[KK-1] = SENT_I;
        }
    }
    // res_* are warp-uniform now.

    // ---- lanes 0..7: per-edge scalar features (parallel over k) ----
    if (lane < KK) {
        float d = SENT_D; int di = 0;
#pragma unroll
        for (int j = 0; j < KK; j++)
            if (lane == j) { d = res_d[j]; di = res_i[j]; }
        bool val = d < 1e9f;
        int dst = val ? di : 0;
        float m = val ? 1.0f : 0.0f;
        int e = i*KK + lane;

        float4 pi = ((const float4*)pos)[i];
        float4 pd = ((const float4*)pos)[dst];
        float cxi = 0.5f*(pi.x+pi.z), cyi = 0.5f*(pi.y+pi.w);
        float cxd = 0.5f*(pd.x+pd.z), cyd = 0.5f*(pd.y+pd.w);
        float wi = pi.z-pi.x, hi = pi.w-pi.y;
        float wd = pd.z-pd.x, hd = pd.w-pd.y;

        float xd = (cxi - cxd) / 1920.0f;
        float yd = (cyi - cyd) / 1080.0f;
        float ix1 = fmaxf(pi.x, pd.x), iy1 = fmaxf(pi.y, pd.y);
        float ix2 = fminf(pi.z, pd.z), iy2 = fminf(pi.w, pd.w);
        float inter = fmaxf(ix2-ix1, 0.0f) * fmaxf(iy2-iy1, 0.0f);
        float iou = inter / (wi*hi + wd*hd - inter + 1e-12f);
        float lw = logf(wi / wd);
        float lh = logf(hi / hd);

        g_head[e*5+0] = xd  * m;
        g_head[e*5+1] = yd  * m;
        g_head[e*5+2] = iou * m;
        g_head[e*5+3] = lw  * m;
        g_head[e*5+4] = lh  * m;
        g_em[e] = make_float2(m, __int_as_float(dst));

        out[EI_OFF + e]       = (float)i;
        out[EI_OFF + NKE + e] = (float)dst;
        out[MASK_OFF + e]     = m;

        // occlusion flag (k == 0 only)
        if (lane == 0) {
            float occf = 0.0f;
            if (val) occf = (inter > wi*hi*0.5f) ? 1.0f : 0.0f;
            out[OCC_OFF + i] = occf;
        }
    }

    // ---- lane 0: topology features (nb_dist, angles) ----
    if (lane == 0) {
        bool val[KK]; float nd[KK], vx[KK], vy[KK];
#pragma unroll
        for (int k = 0; k < KK; k++) {
            val[k] = res_d[k] < 1e9f;
            nd[k]  = val[k] ? res_d[k] : 0.0f;
            int nik = val[k] ? res_i[k] : 0;
            float2 cn = sc[nik];
            vx[k] = cn.x - ci.x;
            vy[k] = cn.y - ci.y;
        }
        float* nf = out + (size_t)i * NFW;
#pragma unroll
        for (int k = 0; k < KK; k++) nf[516 + k] = nd[k] / 1080.0f;

        const float LO = (float)(-1.0 + 1e-6);
        const float HI = (float)( 1.0 - 1e-6);
#pragma unroll
        for (int k = 0; k < KK-1; k++) {
            float a = 0.0f;
            if (val[k+1]) {
                float dot = vx[k]*vx[k+1] + vy[k]*vy[k+1];
                float n1 = sqrtf(vx[k]*vx[k] + vy[k]*vy[k]);
                float n2 = sqrtf(vx[k+1]*vx[k+1] + vy[k+1]*vy[k+1]);
                float cs = dot / (n1*n2 + 1e-12f);
                cs = fminf(fmaxf(cs, LO), HI);
                a = acosf(cs) * 57.29577951308232f;
            }
            nf[524 + k] = a / 360.0f;
        }
        nf[531] = 0.0f;
    }
}

// ---------------------------------------------------------------------------
// K2: flat copy of edge_attr with aligned float4 streaming stores.
//     One thread = one aligned float4 of the 33.7M-float edge_attr region.
// ---------------------------------------------------------------------------
__global__ void __launch_bounds__(256)
k_edge(float* __restrict__ out)
{
    unsigned g4 = blockIdx.x * 256u + threadIdx.x;   // float4 index
    unsigned g  = g4 * 4u;                           // float index in EA
    unsigned e  = g / 1029u;
    unsigned c  = g - e * 1029u;

    const float* nf = out;
    float4 v;

    if (c >= 517u && c <= 1025u) {
        // pure dst-reid quad, same row
        float2 md = g_em[e];
        float m = md.x; int dst = __float_as_int(md.y);
        const float* p = nf + (size_t)dst * NFW + (c - 517u);
        v.x = __ldg(p+0)*m; v.y = __ldg(p+1)*m;
        v.z = __ldg(p+2)*m; v.w = __ldg(p+3)*m;
    } else if (c >= 5u && c + 3u < 517u) {
        // pure src-reid quad, same row
        float m = g_em[e].x;
        unsigned i = e >> 3;
        const float* p = nf + (size_t)i * NFW + (c - 5u);
        v.x = __ldg(p+0)*m; v.y = __ldg(p+1)*m;
        v.z = __ldg(p+2)*m; v.w = __ldg(p+3)*m;
    } else {
        // generic: head cols, region straddles, row crossings
        float vv[4];
#pragma unroll
        for (int j = 0; j < 4; j++) {
            unsigned gg = g + (unsigned)j;
            unsigned ee = gg / 1029u;
            unsigned cc = gg - ee * 1029u;
            float2 md = g_em[ee];
            float mm = md.x; int dd = __float_as_int(md.y);
            unsigned ii = ee >> 3;
            float val;
            if      (cc >= 517u) val = __ldg(nf + (size_t)dd * NFW + (cc - 517u)) * mm;
            else if (cc >= 5u)   val = __ldg(nf + (size_t)ii * NFW + (cc - 5u))   * mm;
            else                 val = g_head[ee*5u + cc];   // pre-masked
            vv[j] = val;
        }
        v = make_float4(vv[0], vv[1], vv[2], vv[3]);
    }

    __stcs((float4*)(out + EA_OFF) + g4, v);
}

// ---------------------------------------------------------------------------
extern "C" void kernel_launch(void* const* d_in, const int* in_sizes, int n_in,
                              void* d_out, int out_size)
{
    const float* reid = (const float*)d_in[0];
    const float* pos  = (const float*)d_in[1];
    float* out = (float*)d_out;

    k_graph<<<Nn/8, 256>>>(reid, pos, out);
    k_edge <<<EATOT/4/256, 256>>>(out);   // 32928 blocks, exact cover
}

// round 6
// speedup vs baseline: 1.8232x; 1.8232x over previous
#include <cuda_runtime.h>
#include <math.h>
#include <stdint.h>

// Problem constants
#define Nn   4096
#define KK   8
#define FD   512
#define NFW  532          // 512 + 4 + 16
#define EAW  1029         // 5 + 2*512
#define NKE  (Nn*KK)      // 32768

// Output layout (flattened float32 concat of the tuple)
#define NF_OFF   ((size_t)0)
#define EI_OFF   ((size_t)Nn*NFW)                 // 2179072
#define EA_OFF   (EI_OFF + (size_t)2*NKE)         // 2244608 (EA_OFF % 4 == 0)
#define OCC_OFF  (EA_OFF + (size_t)NKE*EAW)       // 35962880
#define MASK_OFF (OCC_OFF + (size_t)Nn)           // 35966976

#define DIST_T   108.0f
#define DIST_T2  11666.0f
#define SENT_D   1e30f
#define SENT_I   0x7fffffff

// Spatial bins: 120-px cells, 16 x 9 grid
#define GX 16
#define GY 9
#define CELLS (GX*GY)
#define INV_CELL (1.0f/120.0f)

__device__ float2 g_c   [Nn];        // centers
__device__ int    g_cell[Nn];
__device__ int    g_rank[Nn];
__device__ int    g_cnt2[CELLS];
__device__ int    g_start[CELLS+1];
__device__ float4 g_bc4 [Nn];        // binned: (cx, cy, idx-bits, 0)
__device__ float2 g_em  [NKE];       // (mask, dst-bits)

// ---------------------------------------------------------------------------
// K0: reid L2-normalize + pos_normed; zero bin counters.
// ---------------------------------------------------------------------------
__global__ void __launch_bounds__(256)
k_norm(const float* __restrict__ reid, const float* __restrict__ pos,
       float* __restrict__ out)
{
    if (blockIdx.x == 0 && threadIdx.x < CELLS) g_cnt2[threadIdx.x] = 0;

    int warp = threadIdx.x >> 5, lane = threadIdx.x & 31;
    int i = blockIdx.x * 8 + warp;

    const float4* r = (const float4*)(reid + (size_t)i * FD);
    float4 v[4];
    float s = 0.0f;
#pragma unroll
    for (int u = 0; u < 4; u++) {
        v[u] = r[lane + 32*u];
        s += v[u].x*v[u].x + v[u].y*v[u].y + v[u].z*v[u].z + v[u].w*v[u].w;
    }
#pragma unroll
    for (int o = 16; o > 0; o >>= 1) s += __shfl_xor_sync(0xffffffffu, s, o);
    float inv = 1.0f / (sqrtf(s) + 1e-12f);

    float4* o4 = (float4*)(out + (size_t)i * NFW);
#pragma unroll
    for (int u = 0; u < 4; u++) {
        float4 w = v[u];
        w.x *= inv; w.y *= inv; w.z *= inv; w.w *= inv;
        o4[lane + 32*u] = w;
    }

    if (lane == 0) {
        float4 p = ((const float4*)pos)[i];
        float cx = 0.5f*(p.x+p.z), cy = 0.5f*(p.y+p.w);
        float w = p.z - p.x, h = p.w - p.y;
        float* o = out + (size_t)i * NFW;
        o[512] = cx / 1920.0f;
        o[513] = cy / 1080.0f;
        o[514] = w  / 1920.0f;
        o[515] = h  / 1080.0f;
    }
}

// ---------------------------------------------------------------------------
// K1: centers, cell ids, bin counts (atomics)
// ---------------------------------------------------------------------------
__global__ void __launch_bounds__(256)
k_cnt(const float* __restrict__ pos)
{
    int i = blockIdx.x * 256 + threadIdx.x;
    float4 p = ((const float4*)pos)[i];
    float cx = 0.5f*(p.x+p.z), cy = 0.5f*(p.y+p.w);
    int bx = min((int)(cx * INV_CELL), GX-1);
    int by = min((int)(cy * INV_CELL), GY-1);
    int cell = by * GX + bx;
    g_c[i]    = make_float2(cx, cy);
    g_cell[i] = cell;
    g_rank[i] = atomicAdd(&g_cnt2[cell], 1);
}

// ---------------------------------------------------------------------------
// K2: exclusive scan of 144 cell counts (single block)
// ---------------------------------------------------------------------------
__global__ void k_scan()
{
    __shared__ int s[256];
    int t = threadIdx.x;
    int v = (t < CELLS) ? g_cnt2[t] : 0;
    s[t] = v;
    __syncthreads();
#pragma unroll
    for (int o = 1; o < 256; o <<= 1) {
        int x = (t >= o) ? s[t-o] : 0;
        __syncthreads();
        s[t] += x;
        __syncthreads();
    }
    if (t < CELLS) g_start[t+1] = s[t];
    if (t == 0)    g_start[0] = 0;
}

// ---------------------------------------------------------------------------
// K3: scatter nodes into binned array
// ---------------------------------------------------------------------------
__global__ void __launch_bounds__(256)
k_scat()
{
    int i = blockIdx.x * 256 + threadIdx.x;
    int p = g_start[g_cell[i]] + g_rank[i];
    float2 c = g_c[i];
    g_bc4[p] = make_float4(c.x, c.y, __int_as_float(i), 0.0f);
}

// ---------------------------------------------------------------------------
// K4: KNN over 3x3 cell ring (one warp per node) + topology + occ + edge
//     scalars + edge_index + mask.
// ---------------------------------------------------------------------------
__global__ void __launch_bounds__(256)
k_knn(const float* __restrict__ pos, float* __restrict__ out)
{
    __shared__ int sst[CELLS+1];
    int tid = threadIdx.x;
    if (tid < CELLS+1) sst[tid] = g_start[tid];
    __syncthreads();

    int warp = tid >> 5, lane = tid & 31;
    int i = blockIdx.x * 8 + warp;
    float2 ci = g_c[i];
    int bx = min((int)(ci.x * INV_CELL), GX-1);
    int by = min((int)(ci.y * INV_CELL), GY-1);

    float dist[KK]; int idx[KK];
#pragma unroll
    for (int u = 0; u < KK; u++) { dist[u] = SENT_D; idx[u] = SENT_I; }

    int y0 = max(by-1, 0), y1 = min(by+1, GY-1);
    int x0 = max(bx-1, 0), x1 = min(bx+1, GX-1);
    for (int cy2 = y0; cy2 <= y1; cy2++) {
        for (int cx2 = x0; cx2 <= x1; cx2++) {
            int cell = cy2 * GX + cx2;
            int s = sst[cell], en = sst[cell+1];
            for (int p = s + lane; p < en; p += 32) {
                float4 b = __ldg(&g_bc4[p]);
                int j = __float_as_int(b.z);
                float dx = ci.x - b.x;
                float dy = ci.y - b.y;
                float d2 = dx*dx + dy*dy;
                if (j != i && d2 <= DIST_T2) {
                    float Dv = sqrtf(fmaxf(d2, 1e-12f));
                    if (Dv <= DIST_T) {
                        float kd = Dv; int ki = j;
#pragma unroll
                        for (int u = 0; u < KK; u++) {
                            bool sw = (kd < dist[u]) || (kd == dist[u] && ki < idx[u]);
                            if (sw) {
                                float td = dist[u]; int ti = idx[u];
                                dist[u] = kd; idx[u] = ki;
                                kd = td; ki = ti;
                            }
                        }
                    }
                }
            }
        }
    }

    // warp merge: 8 rounds of packed (distBits, idx) min-reduce
    float res_d[KK]; int res_i[KK];
#pragma unroll
    for (int k = 0; k < KK; k++) {
        unsigned long long key =
            ((unsigned long long)__float_as_uint(dist[0]) << 32) | (unsigned)idx[0];
#pragma unroll
        for (int o = 16; o > 0; o >>= 1) {
            unsigned long long other = __shfl_xor_sync(0xffffffffu, key, o);
            if (other < key) key = other;
        }
        res_d[k] = __uint_as_float((unsigned)(key >> 32));
        res_i[k] = (int)(unsigned)(key & 0xffffffffull);
        unsigned long long mine =
            ((unsigned long long)__float_as_uint(dist[0]) << 32) | (unsigned)idx[0];
        if (mine == key) {
#pragma unroll
            for (int u = 0; u < KK-1; u++) { dist[u] = dist[u+1]; idx[u] = idx[u+1]; }
            dist[KK-1] = SENT_D; idx[KK-1] = SENT_I;
        }
    }
    // res_* now warp-uniform

    // ---- lanes 0..7: per-edge scalar features ----
    if (lane < KK) {
        float d = SENT_D; int di = 0;
#pragma unroll
        for (int j = 0; j < KK; j++)
            if (lane == j) { d = res_d[j]; di = res_i[j]; }
        bool val = d < 1e9f;
        int dst = val ? di : 0;
        float m = val ? 1.0f : 0.0f;
        int e = i*KK + lane;

        float4 pi = ((const float4*)pos)[i];
        float4 pd = ((const float4*)pos)[dst];
        float cxi = 0.5f*(pi.x+pi.z), cyi = 0.5f*(pi.y+pi.w);
        float cxd = 0.5f*(pd.x+pd.z), cyd = 0.5f*(pd.y+pd.w);
        float wi = pi.z-pi.x, hi = pi.w-pi.y;
        float wd = pd.z-pd.x, hd = pd.w-pd.y;

        float xd = (cxi - cxd) / 1920.0f;
        float yd = (cyi - cyd) / 1080.0f;
        float ix1 = fmaxf(pi.x, pd.x), iy1 = fmaxf(pi.y, pd.y);
        float ix2 = fminf(pi.z, pd.z), iy2 = fminf(pi.w, pd.w);
        float inter = fmaxf(ix2-ix1, 0.0f) * fmaxf(iy2-iy1, 0.0f);
        float iou = inter / (wi*hi + wd*hd - inter + 1e-12f);
        float lw = logf(wi / wd);
        float lh = logf(hi / hd);

        float* ea = out + EA_OFF + (size_t)e * EAW;
        ea[0] = xd  * m;
        ea[1] = yd  * m;
        ea[2] = iou * m;
        ea[3] = lw  * m;
        ea[4] = lh  * m;

        g_em[e] = make_float2(m, __int_as_float(dst));
        out[EI_OFF + e]       = (float)i;
        out[EI_OFF + NKE + e] = (float)dst;
        out[MASK_OFF + e]     = m;

        if (lane == 0) {
            float occf = 0.0f;
            if (val) occf = (inter > wi*hi*0.5f) ? 1.0f : 0.0f;
            out[OCC_OFF + i] = occf;
        }
    }

    // ---- lane 0: topology features (nb_dist, angles) ----
    if (lane == 0) {
        bool val[KK]; float nd[KK], vx[KK], vy[KK];
#pragma unroll
        for (int k = 0; k < KK; k++) {
            val[k] = res_d[k] < 1e9f;
            nd[k]  = val[k] ? res_d[k] : 0.0f;
            int nik = val[k] ? res_i[k] : 0;
            float2 cn = g_c[nik];
            vx[k] = cn.x - ci.x;
            vy[k] = cn.y - ci.y;
        }
        float* nf = out + (size_t)i * NFW;
#pragma unroll
        for (int k = 0; k < KK; k++) nf[516 + k] = nd[k] / 1080.0f;

        const float LO = (float)(-1.0 + 1e-6);
        const float HI = (float)( 1.0 - 1e-6);
#pragma unroll
        for (int k = 0; k < KK-1; k++) {
            float a = 0.0f;
            if (val[k+1]) {
                float dot = vx[k]*vx[k+1] + vy[k]*vy[k+1];
                float n1 = sqrtf(vx[k]*vx[k] + vy[k]*vy[k]);
                float n2 = sqrtf(vx[k+1]*vx[k+1] + vy[k+1]*vy[k+1]);
                float cs = dot / (n1*n2 + 1e-12f);
                cs = fminf(fmaxf(cs, LO), HI);
                a = acosf(cs) * 57.29577951308232f;
            }
            nf[524 + k] = a / 360.0f;
        }
        nf[531] = 0.0f;
    }
}

// ---------------------------------------------------------------------------
// K5: bulk reid copy. One warp per edge. Aligned float4 loads, shuffle-rotate,
//     aligned float4 streaming stores.
// ---------------------------------------------------------------------------
__global__ void __launch_bounds__(256)
k_edge(float* __restrict__ out)
{
    const unsigned FULL = 0xffffffffu;
    int warp = threadIdx.x >> 5, lane = threadIdx.x & 31;
    int e = blockIdx.x * 8 + warp;
    int i = e >> 3;

    float2 md = g_em[e];
    float m  = md.x;
    int  dst = __float_as_int(md.y);

    const float* nf = out;
    const float4* rs4 = (const float4*)(nf + (size_t)i   * NFW);
    const float4* rd4 = (const float4*)(nf + (size_t)dst * NFW);

    // Combined logical row R[0..1024): src[0..512) ++ dst[0..512).
    // Lane holds F[lane + 32u], F[Q] = Q<128 ? src4[Q] : dst4[Q-128].
    float4 v[8];
#pragma unroll
    for (int u = 0; u < 4; u++) v[u]   = __ldg(rs4 + lane + 32*u);
#pragma unroll
    for (int u = 0; u < 4; u++) v[u+4] = __ldg(rd4 + lane + 32*u);

    size_t B = EA_OFF + (size_t)e * EAW;       // row base (float index)
    int r = (e + 1) & 3;                       // (B+5) mod 4
    int a = (4 - r) & 3;                       // leading scalars
    int Qn = a ? 255 : 256;                    // interior aligned quads
    float4* ea4 = (float4*)(out + B + 5 + a);

    if (a == 0) {
#pragma unroll
        for (int u = 0; u < 8; u++) {
            float4 f = v[u];
            f.x *= m; f.y *= m; f.z *= m; f.w *= m;
            __stcs(ea4 + lane + 32*u, f);
        }
    } else {
#pragma unroll
        for (int u = 0; u < 8; u++) {
            float4 f = v[u];
            // n = F[q+1]
            float4 n;
            n.x = __shfl_sync(FULL, v[u].x, lane + 1);
            n.y = __shfl_sync(FULL, v[u].y, lane + 1);
            n.z = __shfl_sync(FULL, v[u].z, lane + 1);
            n.w = __shfl_sync(FULL, v[u].w, lane + 1);
            int un = (u + 1) & 7;
            float4 f0;
            f0.x = __shfl_sync(FULL, v[un].x, 0);
            f0.y = __shfl_sync(FULL, v[un].y, 0);
            f0.z = __shfl_sync(FULL, v[un].z, 0);
            f0.w = __shfl_sync(FULL, v[un].w, 0);
            if (lane == 31) n = f0;

            float4 o;
            if      (a == 1) o = make_float4(f.y, f.z, f.w, n.x);
            else if (a == 2) o = make_float4(f.z, f.w, n.x, n.y);
            else             o = make_float4(f.w, n.x, n.y, n.z);

            int q = lane + 32*u;
            if (q < Qn) {
                o.x *= m; o.y *= m; o.z *= m; o.w *= m;
                __stcs(ea4 + q, o);
            }
        }
        // head scalars: cols 5..5+a-1  <- src[0..a)
        if (lane < a)
            __stcs(out + B + 5 + lane, __ldg(nf + (size_t)i * NFW + lane) * m);
        // tail scalars: cols 1025+a..1028 <- dst[508+a..512)
        int t = 4 - a;
        if (lane < t)
            __stcs(out + B + 1025 + a + lane,
                   __ldg(nf + (size_t)dst * NFW + 508 + a + lane) * m);
    }
}

// ---------------------------------------------------------------------------
extern "C" void kernel_launch(void* const* d_in, const int* in_sizes, int n_in,
                              void* d_out, int out_size)
{
    const float* reid = (const float*)d_in[0];
    const float* pos  = (const float*)d_in[1];
    float* out = (float*)d_out;

    k_norm<<<Nn/8, 256>>>(reid, pos, out);
    k_cnt <<<Nn/256, 256>>>(pos);
    k_scan<<<1, 256>>>();
    k_scat<<<Nn/256, 256>>>();
    k_knn <<<Nn/8, 256>>>(pos, out);
    k_edge<<<NKE/8, 256>>>(out);
}

// round 7
// speedup vs baseline: 1.8459x; 1.0125x over previous
#include <cuda_runtime.h>
#include <math.h>
#include <stdint.h>

// Problem constants
#define Nn   4096
#define KK   8
#define FD   512
#define NFW  532          // 512 + 4 + 16
#define EAW  1029         // 5 + 2*512
#define NKE  (Nn*KK)      // 32768

// Output layout (flattened float32 concat of the tuple)
#define NF_OFF   ((size_t)0)
#define EI_OFF   ((size_t)Nn*NFW)                 // 2179072
#define EA_OFF   (EI_OFF + (size_t)2*NKE)         // 2244608 (EA_OFF % 4 == 0)
#define OCC_OFF  (EA_OFF + (size_t)NKE*EAW)       // 35962880
#define MASK_OFF (OCC_OFF + (size_t)Nn)           // 35966976

#define DIST_T   108.0f
#define DIST_T2  11666.0f
#define SENT_D   1e30f
#define SENT_I   0x7fffffff

// Spatial bins: 120-px cells, 16 x 9 grid
#define GX 16
#define GY 9
#define CELLS (GX*GY)
#define INV_CELL (1.0f/120.0f)

__device__ float2 g_c    [Nn];
__device__ int    g_start[CELLS+1];
__device__ float4 g_bc4  [Nn];       // binned: (cx, cy, idx-bits, 0)
__device__ float2 g_em   [NKE];      // (mask, dst-bits)
__device__ float  g_head [NKE*5];    // pre-masked per-edge scalars

// ---------------------------------------------------------------------------
// K0: reid L2-normalize + pos_normed
// ---------------------------------------------------------------------------
__global__ void __launch_bounds__(256)
k_norm(const float* __restrict__ reid, const float* __restrict__ pos,
       float* __restrict__ out)
{
    int warp = threadIdx.x >> 5, lane = threadIdx.x & 31;
    int i = blockIdx.x * 8 + warp;

    const float4* r = (const float4*)(reid + (size_t)i * FD);
    float4 v[4];
    float s = 0.0f;
#pragma unroll
    for (int u = 0; u < 4; u++) {
        v[u] = r[lane + 32*u];
        s += v[u].x*v[u].x + v[u].y*v[u].y + v[u].z*v[u].z + v[u].w*v[u].w;
    }
#pragma unroll
    for (int o = 16; o > 0; o >>= 1) s += __shfl_xor_sync(0xffffffffu, s, o);
    float inv = 1.0f / (sqrtf(s) + 1e-12f);

    float4* o4 = (float4*)(out + (size_t)i * NFW);
#pragma unroll
    for (int u = 0; u < 4; u++) {
        float4 w = v[u];
        w.x *= inv; w.y *= inv; w.z *= inv; w.w *= inv;
        o4[lane + 32*u] = w;
    }

    if (lane == 0) {
        float4 p = ((const float4*)pos)[i];
        float cx = 0.5f*(p.x+p.z), cy = 0.5f*(p.y+p.w);
        float w = p.z - p.x, h = p.w - p.y;
        float* o = out + (size_t)i * NFW;
        o[512] = cx / 1920.0f;
        o[513] = cy / 1080.0f;
        o[514] = w  / 1920.0f;
        o[515] = h  / 1080.0f;
    }
}

// ---------------------------------------------------------------------------
// K1: fused binning (count + scan + scatter) in ONE single-block kernel.
// ---------------------------------------------------------------------------
__global__ void __launch_bounds__(1024)
k_bin(const float* __restrict__ pos)
{
    __shared__ float2 scen[Nn];          // 32 KB
    __shared__ short  srank[Nn];         // 8 KB
    __shared__ int    scnt[CELLS];
    __shared__ int    s[256];
    __shared__ int    sstart[CELLS+1];

    int tid = threadIdx.x;
    if (tid < CELLS) scnt[tid] = 0;
    __syncthreads();

#pragma unroll
    for (int ii = 0; ii < 4; ii++) {
        int i = tid + 1024*ii;
        float4 p = ((const float4*)pos)[i];
        float cx = 0.5f*(p.x+p.z), cy = 0.5f*(p.y+p.w);
        float2 c = make_float2(cx, cy);
        scen[i] = c;
        g_c[i]  = c;
        int bx = min((int)(cx * INV_CELL), GX-1);
        int by = min((int)(cy * INV_CELL), GY-1);
        srank[i] = (short)atomicAdd(&scnt[by*GX + bx], 1);
    }
    __syncthreads();

    // Hillis-Steele inclusive scan over 256 slots
    if (tid < 256) s[tid] = (tid < CELLS) ? scnt[tid] : 0;
    __syncthreads();
#pragma unroll
    for (int o = 1; o < 256; o <<= 1) {
        int x = (tid < 256 && tid >= o) ? s[tid-o] : 0;
        __syncthreads();
        if (tid < 256) s[tid] += x;
        __syncthreads();
    }
    if (tid < CELLS) { sstart[tid+1] = s[tid]; g_start[tid+1] = s[tid]; }
    if (tid == 0)    { sstart[0] = 0;          g_start[0] = 0; }
    __syncthreads();

#pragma unroll
    for (int ii = 0; ii < 4; ii++) {
        int i = tid + 1024*ii;
        float2 c = scen[i];
        int bx = min((int)(c.x * INV_CELL), GX-1);
        int by = min((int)(c.y * INV_CELL), GY-1);
        int p = sstart[by*GX + bx] + (int)srank[i];
        g_bc4[p] = make_float4(c.x, c.y, __int_as_float(i), 0.0f);
    }
}

// ---------------------------------------------------------------------------
// K2: KNN over 3x3 cell ring (one warp per node) + topology + occ +
//     edge scalar stash + edge_index + mask.
// ---------------------------------------------------------------------------
__global__ void __launch_bounds__(256)
k_knn(const float* __restrict__ pos, float* __restrict__ out)
{
    __shared__ int sst[CELLS+1];
    int tid = threadIdx.x;
    if (tid < CELLS+1) sst[tid] = g_start[tid];
    __syncthreads();

    int warp = tid >> 5, lane = tid & 31;
    int i = blockIdx.x * 8 + warp;
    float2 ci = g_c[i];
    int bx = min((int)(ci.x * INV_CELL), GX-1);
    int by = min((int)(ci.y * INV_CELL), GY-1);

    float dist[KK]; int idx[KK];
#pragma unroll
    for (int u = 0; u < KK; u++) { dist[u] = SENT_D; idx[u] = SENT_I; }

    int y0 = max(by-1, 0), y1 = min(by+1, GY-1);
    int x0 = max(bx-1, 0), x1 = min(bx+1, GX-1);
    for (int cy2 = y0; cy2 <= y1; cy2++) {
        for (int cx2 = x0; cx2 <= x1; cx2++) {
            int cell = cy2 * GX + cx2;
            int st = sst[cell], en = sst[cell+1];
            for (int p = st + lane; p < en; p += 32) {
                float4 b = __ldg(&g_bc4[p]);
                int j = __float_as_int(b.z);
                float dx = ci.x - b.x;
                float dy = ci.y - b.y;
                float d2 = dx*dx + dy*dy;
                if (j != i && d2 <= DIST_T2) {
                    float Dv = sqrtf(fmaxf(d2, 1e-12f));
                    if (Dv <= DIST_T) {
                        float kd = Dv; int ki = j;
#pragma unroll
                        for (int u = 0; u < KK; u++) {
                            bool sw = (kd < dist[u]) || (kd == dist[u] && ki < idx[u]);
                            if (sw) {
                                float td = dist[u]; int ti = idx[u];
                                dist[u] = kd; idx[u] = ki;
                                kd = td; ki = ti;
                            }
                        }
                    }
                }
            }
        }
    }

    // warp merge: 8 rounds of packed (distBits, idx) min-reduce
    float res_d[KK]; int res_i[KK];
#pragma unroll
    for (int k = 0; k < KK; k++) {
        unsigned long long key =
            ((unsigned long long)__float_as_uint(dist[0]) << 32) | (unsigned)idx[0];
#pragma unroll
        for (int o = 16; o > 0; o >>= 1) {
            unsigned long long other = __shfl_xor_sync(0xffffffffu, key, o);
            if (other < key) key = other;
        }
        res_d[k] = __uint_as_float((unsigned)(key >> 32));
        res_i[k] = (int)(unsigned)(key & 0xffffffffull);
        unsigned long long mine =
            ((unsigned long long)__float_as_uint(dist[0]) << 32) | (unsigned)idx[0];
        if (mine == key) {
#pragma unroll
            for (int u = 0; u < KK-1; u++) { dist[u] = dist[u+1]; idx[u] = idx[u+1]; }
            dist[KK-1] = SENT_D; idx[KK-1] = SENT_I;
        }
    }
    // res_* now warp-uniform

    // ---- lanes 0..7: per-edge scalar stash ----
    if (lane < KK) {
        float d = SENT_D; int di = 0;
#pragma unroll
        for (int j = 0; j < KK; j++)
            if (lane == j) { d = res_d[j]; di = res_i[j]; }
        bool val = d < 1e9f;
        int dst = val ? di : 0;
        float m = val ? 1.0f : 0.0f;
        int e = i*KK + lane;

        float4 pi = ((const float4*)pos)[i];
        float4 pd = ((const float4*)pos)[dst];
        float cxi = 0.5f*(pi.x+pi.z), cyi = 0.5f*(pi.y+pi.w);
        float cxd = 0.5f*(pd.x+pd.z), cyd = 0.5f*(pd.y+pd.w);
        float wi = pi.z-pi.x, hi = pi.w-pi.y;
        float wd = pd.z-pd.x, hd = pd.w-pd.y;

        float xd = (cxi - cxd) / 1920.0f;
        float yd = (cyi - cyd) / 1080.0f;
        float ix1 = fmaxf(pi.x, pd.x), iy1 = fmaxf(pi.y, pd.y);
        float ix2 = fminf(pi.z, pd.z), iy2 = fminf(pi.w, pd.w);
        float inter = fmaxf(ix2-ix1, 0.0f) * fmaxf(iy2-iy1, 0.0f);
        float iou = inter / (wi*hi + wd*hd - inter + 1e-12f);
        float lw = logf(wi / wd);
        float lh = logf(hi / hd);

        g_head[e*5+0] = xd  * m;
        g_head[e*5+1] = yd  * m;
        g_head[e*5+2] = iou * m;
        g_head[e*5+3] = lw  * m;
        g_head[e*5+4] = lh  * m;
        g_em[e] = make_float2(m, __int_as_float(dst));

        out[EI_OFF + e]       = (float)i;
        out[EI_OFF + NKE + e] = (float)dst;
        out[MASK_OFF + e]     = m;

        if (lane == 0) {
            float occf = 0.0f;
            if (val) occf = (inter > wi*hi*0.5f) ? 1.0f : 0.0f;
            out[OCC_OFF + i] = occf;
        }
    }

    // ---- lane 0: topology features (nb_dist, angles) ----
    if (lane == 0) {
        bool val[KK]; float nd[KK], vx[KK], vy[KK];
#pragma unroll
        for (int k = 0; k < KK; k++) {
            val[k] = res_d[k] < 1e9f;
            nd[k]  = val[k] ? res_d[k] : 0.0f;
            int nik = val[k] ? res_i[k] : 0;
            float2 cn = g_c[nik];
            vx[k] = cn.x - ci.x;
            vy[k] = cn.y - ci.y;
        }
        float* nf = out + (size_t)i * NFW;
#pragma unroll
        for (int k = 0; k < KK; k++) nf[516 + k] = nd[k] / 1080.0f;

        const float LO = (float)(-1.0 + 1e-6);
        const float HI = (float)( 1.0 - 1e-6);
#pragma unroll
        for (int k = 0; k < KK-1; k++) {
            float a = 0.0f;
            if (val[k+1]) {
                float dot = vx[k]*vx[k+1] + vy[k]*vy[k+1];
                float n1 = sqrtf(vx[k]*vx[k] + vy[k]*vy[k]);
                float n2 = sqrtf(vx[k+1]*vx[k+1] + vy[k+1]*vy[k+1]);
                float cs = dot / (n1*n2 + 1e-12f);
                cs = fminf(fmaxf(cs, LO), HI);
                a = acosf(cs) * 57.29577951308232f;
            }
            nf[524 + k] = a / 360.0f;
        }
        nf[531] = 0.0f;
    }
}

// ---------------------------------------------------------------------------
// K3: bulk reid copy + head scalars. TWO warps per edge (src half / dst half).
//     Aligned float4 loads, shuffle-rotate, aligned float4 streaming stores.
// ---------------------------------------------------------------------------
__global__ void __launch_bounds__(256)
k_edge(float* __restrict__ out)
{
    const unsigned FULL = 0xffffffffu;
    int wp = threadIdx.x >> 5, lane = threadIdx.x & 31;
    int e = blockIdx.x * 4 + (wp >> 1);
    int half = wp & 1;                   // 0 = src half, 1 = dst half
    int i = e >> 3;

    float2 md = g_em[e];
    float m  = md.x;
    int  dst = __float_as_int(md.y);

    const float* nf = out;
    size_t B = EA_OFF + (size_t)e * EAW;
    int r = (e + 1) & 3;                 // (B+5) mod 4
    int a = (4 - r) & 3;                 // leading scalar count
    float4* ea4 = (float4*)(out + B + 5 + a);

    if (half == 0) {
        const float4* rs4 = (const float4*)(nf + (size_t)i * NFW);
        float4 v[4];
#pragma unroll
        for (int u = 0; u < 4; u++) v[u] = __ldg(rs4 + lane + 32*u);

        if (a == 0) {
#pragma unroll
            for (int u = 0; u < 4; u++) {
                float4 f = v[u];
                f.x *= m; f.y *= m; f.z *= m; f.w *= m;
                __stcs(ea4 + lane + 32*u, f);
            }
        } else {
            float4 e4 = __ldg((const float4*)(nf + (size_t)dst * NFW)); // dst quad 0
#pragma unroll
            for (int u = 0; u < 4; u++) {
                float4 f = v[u];
                float4 n;
                n.x = __shfl_sync(FULL, v[u].x, lane + 1);
                n.y = __shfl_sync(FULL, v[u].y, lane + 1);
                n.z = __shfl_sync(FULL, v[u].z, lane + 1);
                n.w = __shfl_sync(FULL, v[u].w, lane + 1);
                float4 f0;
                if (u < 3) {
                    f0.x = __shfl_sync(FULL, v[(u+1)&3].x, 0);
                    f0.y = __shfl_sync(FULL, v[(u+1)&3].y, 0);
                    f0.z = __shfl_sync(FULL, v[(u+1)&3].z, 0);
                    f0.w = __shfl_sync(FULL, v[(u+1)&3].w, 0);
                } else {
                    f0 = e4;
                }
                if (lane == 31) n = f0;

                float4 o;
                if      (a == 1) o = make_float4(f.y, f.z, f.w, n.x);
                else if (a == 2) o = make_float4(f.z, f.w, n.x, n.y);
                else             o = make_float4(f.w, n.x, n.y, n.z);
                o.x *= m; o.y *= m; o.z *= m; o.w *= m;
                __stcs(ea4 + lane + 32*u, o);     // q in [0,128) < Qn always
            }
        }
        // head: cols 0..4 <- g_head; cols 5..5+a-1 <- src[0..a)
        if (lane < 5)
            __stcs(out + B + lane, g_head[e*5 + lane]);
        else if (lane < 5 + a)
            __stcs(out + B + lane, __ldg(nf + (size_t)i * NFW + (lane - 5)) * m);
    } else {
        const float4* rd4 = (const float4*)(nf + (size_t)dst * NFW);
        float4 v[4];
#pragma unroll
        for (int u = 0; u < 4; u++) v[u] = __ldg(rd4 + lane + 32*u);

        if (a == 0) {
#pragma unroll
            for (int u = 0; u < 4; u++) {
                float4 f = v[u];
                f.x *= m; f.y *= m; f.z *= m; f.w *= m;
                __stcs(ea4 + lane + 32*(u+4), f);
            }
        } else {
#pragma unroll
            for (int u = 0; u < 4; u++) {
                float4 f = v[u];
                float4 n;
                n.x = __shfl_sync(FULL, v[u].x, lane + 1);
                n.y = __shfl_sync(FULL, v[u].y, lane + 1);
                n.z = __shfl_sync(FULL, v[u].z, lane + 1);
                n.w = __shfl_sync(FULL, v[u].w, lane + 1);
                float4 f0;
                f0.x = __shfl_sync(FULL, v[(u+1)&3].x, 0);
                f0.y = __shfl_sync(FULL, v[(u+1)&3].y, 0);
                f0.z = __shfl_sync(FULL, v[(u+1)&3].z, 0);
                f0.w = __shfl_sync(FULL, v[(u+1)&3].w, 0);
                if (lane == 31) n = f0;

                float4 o;
                if      (a == 1) o = make_float4(f.y, f.z, f.w, n.x);
                else if (a == 2) o = make_float4(f.z, f.w, n.x, n.y);
                else             o = make_float4(f.w, n.x, n.y, n.z);

                int q = lane + 32*(u+4);
                if (q < 255) {                    // last combined quad excluded
                    o.x *= m; o.y *= m; o.z *= m; o.w *= m;
                    __stcs(ea4 + q, o);
                }
            }
            // tail: cols 1025+a..1028 <- dst[508+a..512)
            int t = 4 - a;
            if (lane < t)
                __stcs(out + B + 1025 + a + lane,
                       __ldg(nf + (size_t)dst * NFW + 508 + a + lane) * m);
        }
    }
}

// ---------------------------------------------------------------------------
extern "C" void kernel_launch(void* const* d_in, const int* in_sizes, int n_in,
                              void* d_out, int out_size)
{
    const float* reid = (const float*)d_in[0];
    const float* pos  = (const float*)d_in[1];
    float* out = (float*)d_out;

    k_norm<<<Nn/8, 256>>>(reid, pos, out);
    k_bin <<<1, 1024>>>(pos);
    k_knn <<<Nn/8, 256>>>(pos, out);
    k_edge<<<NKE/4, 256>>>(out);
}

// round 8
// speedup vs baseline: 1.9793x; 1.0722x over previous
#include <cuda_runtime.h>
#include <math.h>
#include <stdint.h>

// Problem constants
#define Nn   4096
#define KK   8
#define FD   512
#define NFW  532          // 512 + 4 + 16
#define EAW  1029         // 5 + 2*512
#define NKE  (Nn*KK)      // 32768

// Output layout (flattened float32 concat of the tuple)
#define NF_OFF   ((size_t)0)
#define EI_OFF   ((size_t)Nn*NFW)                 // 2179072
#define EA_OFF   (EI_OFF + (size_t)2*NKE)         // 2244608 (EA_OFF % 4 == 0)
#define OCC_OFF  (EA_OFF + (size_t)NKE*EAW)       // 35962880
#define MASK_OFF (OCC_OFF + (size_t)Nn)           // 35966976

#define DIST_T   108.0f
#define DIST_T2  11666.0f
#define SENT_D   1e30f
#define SENT_I   0x7fffffff

// Spatial bins: 120-px cells, 16 x 9 grid
#define GX 16
#define GY 9
#define CELLS (GX*GY)
#define INV_CELL (1.0f/120.0f)

__device__ float2 g_c    [Nn];
__device__ int    g_start[CELLS+1];
__device__ float4 g_bc4  [Nn];       // binned: (cx, cy, idx-bits, 0)
__device__ float2 g_em   [NKE];      // (mask, dst-bits)
__device__ float  g_head [NKE*5];    // pre-masked per-edge scalars
__device__ int    g_flag = 0;        // bin-done flag (reset by k_edge)

// ===========================================================================
// MEGA kernel: block 0 = binning; blocks 1..512 = reid norm;
//              blocks 513..1024 = KNN (spin-wait on bin flag).
// ===========================================================================
__global__ void __launch_bounds__(256)
k_mega(const float* __restrict__ reid, const float* __restrict__ pos,
       float* __restrict__ out)
{
    __shared__ short srank[Nn];          // 8 KB (bin only)
    __shared__ int   scnt [CELLS];
    __shared__ int   sscan[256];
    __shared__ int   sst  [CELLS+1];     // bin: starts; knn: cached starts

    int tid = threadIdx.x;
    int bid = blockIdx.x;
    int warp = tid >> 5, lane = tid & 31;

    if (bid == 0) {
        // ------------------- BINNING (count + scan + scatter) -------------
        if (tid < CELLS) scnt[tid] = 0;
        __syncthreads();

#pragma unroll
        for (int ii = 0; ii < 16; ii++) {
            int i = tid + 256*ii;
            float4 p = ((const float4*)pos)[i];
            float cx = 0.5f*(p.x+p.z), cy = 0.5f*(p.y+p.w);
            g_c[i] = make_float2(cx, cy);
            int bx = min((int)(cx * INV_CELL), GX-1);
            int by = min((int)(cy * INV_CELL), GY-1);
            srank[i] = (short)atomicAdd(&scnt[by*GX + bx], 1);
        }
        __syncthreads();

        // Hillis-Steele inclusive scan over 256 slots
        sscan[tid] = (tid < CELLS) ? scnt[tid] : 0;
        __syncthreads();
#pragma unroll
        for (int o = 1; o < 256; o <<= 1) {
            int x = (tid >= o) ? sscan[tid-o] : 0;
            __syncthreads();
            sscan[tid] += x;
            __syncthreads();
        }
        if (tid < CELLS) { sst[tid+1] = sscan[tid]; g_start[tid+1] = sscan[tid]; }
        if (tid == 0)    { sst[0] = 0;              g_start[0] = 0; }
        __syncthreads();

#pragma unroll
        for (int ii = 0; ii < 16; ii++) {
            int i = tid + 256*ii;
            float2 c = g_c[i];
            int bx = min((int)(c.x * INV_CELL), GX-1);
            int by = min((int)(c.y * INV_CELL), GY-1);
            int p = sst[by*GX + bx] + (int)srank[i];
            g_bc4[p] = make_float4(c.x, c.y, __int_as_float(i), 0.0f);
        }
        __syncthreads();
        __threadfence();
        if (tid == 0) atomicExch(&g_flag, 1);
        return;
    }

    if (bid <= 512) {
        // ------------------- REID NORM + pos_normed -----------------------
        int i = (bid - 1) * 8 + warp;

        const float4* r = (const float4*)(reid + (size_t)i * FD);
        float4 v[4];
        float s = 0.0f;
#pragma unroll
        for (int u = 0; u < 4; u++) {
            v[u] = r[lane + 32*u];
            s += v[u].x*v[u].x + v[u].y*v[u].y + v[u].z*v[u].z + v[u].w*v[u].w;
        }
#pragma unroll
        for (int o = 16; o > 0; o >>= 1) s += __shfl_xor_sync(0xffffffffu, s, o);
        float inv = 1.0f / (sqrtf(s) + 1e-12f);

        float4* o4 = (float4*)(out + (size_t)i * NFW);
#pragma unroll
        for (int u = 0; u < 4; u++) {
            float4 w = v[u];
            w.x *= inv; w.y *= inv; w.z *= inv; w.w *= inv;
            o4[lane + 32*u] = w;
        }

        if (lane == 0) {
            float4 p = ((const float4*)pos)[i];
            float cx = 0.5f*(p.x+p.z), cy = 0.5f*(p.y+p.w);
            float w = p.z - p.x, h = p.w - p.y;
            float* o = out + (size_t)i * NFW;
            o[512] = cx / 1920.0f;
            o[513] = cy / 1080.0f;
            o[514] = w  / 1920.0f;
            o[515] = h  / 1080.0f;
        }
        return;
    }

    // ----------------------- KNN (wait for binning) -----------------------
    if (tid == 0) {
        while (atomicAdd(&g_flag, 0) == 0) { __nanosleep(64); }
    }
    __syncthreads();
    __threadfence();

    if (tid < CELLS+1) sst[tid] = g_start[tid];
    __syncthreads();

    int i = (bid - 513) * 8 + warp;
    float2 ci = g_c[i];
    int bx = min((int)(ci.x * INV_CELL), GX-1);
    int by = min((int)(ci.y * INV_CELL), GY-1);

    float dist[KK]; int idx[KK];
#pragma unroll
    for (int u = 0; u < KK; u++) { dist[u] = SENT_D; idx[u] = SENT_I; }

    int y0 = max(by-1, 0), y1 = min(by+1, GY-1);
    int x0 = max(bx-1, 0), x1 = min(bx+1, GX-1);
    for (int cy2 = y0; cy2 <= y1; cy2++) {
        // cells in a grid row are contiguous in the binned array
        int st = sst[cy2*GX + x0], en = sst[cy2*GX + x1 + 1];
        for (int p = st + lane; p < en; p += 32) {
            float4 b = __ldg(&g_bc4[p]);
            int j = __float_as_int(b.z);
            float dx = ci.x - b.x;
            float dy = ci.y - b.y;
            float d2 = dx*dx + dy*dy;
            if (j != i && d2 <= DIST_T2) {
                float Dv = sqrtf(fmaxf(d2, 1e-12f));
                if (Dv <= DIST_T) {
                    float kd = Dv; int ki = j;
#pragma unroll
                    for (int u = 0; u < KK; u++) {
                        bool sw = (kd < dist[u]) || (kd == dist[u] && ki < idx[u]);
                        if (sw) {
                            float td = dist[u]; int ti = idx[u];
                            dist[u] = kd; idx[u] = ki;
                            kd = td; ki = ti;
                        }
                    }
                }
            }
        }
    }

    // warp merge: 8 rounds of packed (distBits, idx) min-reduce
    float res_d[KK]; int res_i[KK];
#pragma unroll
    for (int k = 0; k < KK; k++) {
        unsigned long long key =
            ((unsigned long long)__float_as_uint(dist[0]) << 32) | (unsigned)idx[0];
#pragma unroll
        for (int o = 16; o > 0; o >>= 1) {
            unsigned long long other = __shfl_xor_sync(0xffffffffu, key, o);
            if (other < key) key = other;
        }
        res_d[k] = __uint_as_float((unsigned)(key >> 32));
        res_i[k] = (int)(unsigned)(key & 0xffffffffull);
        unsigned long long mine =
            ((unsigned long long)__float_as_uint(dist[0]) << 32) | (unsigned)idx[0];
        if (mine == key) {
#pragma unroll
            for (int u = 0; u < KK-1; u++) { dist[u] = dist[u+1]; idx[u] = idx[u+1]; }
            dist[KK-1] = SENT_D; idx[KK-1] = SENT_I;
        }
    }
    // res_* now warp-uniform

    // ---- lanes 0..7: per-edge scalar stash ----
    if (lane < KK) {
        float d = SENT_D; int di = 0;
#pragma unroll
        for (int j = 0; j < KK; j++)
            if (lane == j) { d = res_d[j]; di = res_i[j]; }
        bool val = d < 1e9f;
        int dst = val ? di : 0;
        float m = val ? 1.0f : 0.0f;
        int e = i*KK + lane;

        float4 pi = ((const float4*)pos)[i];
        float4 pd = ((const float4*)pos)[dst];
        float cxi = 0.5f*(pi.x+pi.z), cyi = 0.5f*(pi.y+pi.w);
        float cxd = 0.5f*(pd.x+pd.z), cyd = 0.5f*(pd.y+pd.w);
        float wi = pi.z-pi.x, hi = pi.w-pi.y;
        float wd = pd.z-pd.x, hd = pd.w-pd.y;

        float xd = (cxi - cxd) / 1920.0f;
        float yd = (cyi - cyd) / 1080.0f;
        float ix1 = fmaxf(pi.x, pd.x), iy1 = fmaxf(pi.y, pd.y);
        float ix2 = fminf(pi.z, pd.z), iy2 = fminf(pi.w, pd.w);
        float inter = fmaxf(ix2-ix1, 0.0f) * fmaxf(iy2-iy1, 0.0f);
        float iou = inter / (wi*hi + wd*hd - inter + 1e-12f);
        float lw = logf(wi / wd);
        float lh = logf(hi / hd);

        g_head[e*5+0] = xd  * m;
        g_head[e*5+1] = yd  * m;
        g_head[e*5+2] = iou * m;
        g_head[e*5+3] = lw  * m;
        g_head[e*5+4] = lh  * m;
        g_em[e] = make_float2(m, __int_as_float(dst));

        out[EI_OFF + e]       = (float)i;
        out[EI_OFF + NKE + e] = (float)dst;
        out[MASK_OFF + e]     = m;

        if (lane == 0) {
            float occf = 0.0f;
            if (val) occf = (inter > wi*hi*0.5f) ? 1.0f : 0.0f;
            out[OCC_OFF + i] = occf;
        }
    }

    // ---- lane 0: topology features (nb_dist, angles) ----
    if (lane == 0) {
        bool val[KK]; float nd[KK], vx[KK], vy[KK];
#pragma unroll
        for (int k = 0; k < KK; k++) {
            val[k] = res_d[k] < 1e9f;
            nd[k]  = val[k] ? res_d[k] : 0.0f;
            int nik = val[k] ? res_i[k] : 0;
            float2 cn = g_c[nik];
            vx[k] = cn.x - ci.x;
            vy[k] = cn.y - ci.y;
        }
        float* nf = out + (size_t)i * NFW;
#pragma unroll
        for (int k = 0; k < KK; k++) nf[516 + k] = nd[k] / 1080.0f;

        const float LO = (float)(-1.0 + 1e-6);
        const float HI = (float)( 1.0 - 1e-6);
#pragma unroll
        for (int k = 0; k < KK-1; k++) {
            float a = 0.0f;
            if (val[k+1]) {
                float dot = vx[k]*vx[k+1] + vy[k]*vy[k+1];
                float n1 = sqrtf(vx[k]*vx[k] + vy[k]*vy[k]);
                float n2 = sqrtf(vx[k+1]*vx[k+1] + vy[k+1]*vy[k+1]);
                float cs = dot / (n1*n2 + 1e-12f);
                cs = fminf(fmaxf(cs, LO), HI);
                a = acosf(cs) * 57.29577951308232f;
            }
            nf[524 + k] = a / 360.0f;
        }
        nf[531] = 0.0f;
    }
}

// ===========================================================================
// K_EDGE: bulk reid copy + head scalars. TWO warps per edge.
//         Aligned float4 loads, shuffle-rotate, aligned float4 stores.
//         (unchanged from R7 except: resets g_flag for next graph replay)
// ===========================================================================
__global__ void __launch_bounds__(256)
k_edge(float* __restrict__ out)
{
    if (blockIdx.x == 0 && threadIdx.x == 0) g_flag = 0;  // reset for replay

    const unsigned FULL = 0xffffffffu;
    int wp = threadIdx.x >> 5, lane = threadIdx.x & 31;
    int e = blockIdx.x * 4 + (wp >> 1);
    int half = wp & 1;                   // 0 = src half, 1 = dst half
    int i = e >> 3;

    float2 md = g_em[e];
    float m  = md.x;
    int  dst = __float_as_int(md.y);

    const float* nf = out;
    size_t B = EA_OFF + (size_t)e * EAW;
    int r = (e + 1) & 3;                 // (B+5) mod 4
    int a = (4 - r) & 3;                 // leading scalar count
    float4* ea4 = (float4*)(out + B + 5 + a);

    if (half == 0) {
        const float4* rs4 = (const float4*)(nf + (size_t)i * NFW);
        float4 v[4];
#pragma unroll
        for (int u = 0; u < 4; u++) v[u] = __ldg(rs4 + lane + 32*u);

        if (a == 0) {
#pragma unroll
            for (int u = 0; u < 4; u++) {
                float4 f = v[u];
                f.x *= m; f.y *= m; f.z *= m; f.w *= m;
                __stcs(ea4 + lane + 32*u, f);
            }
        } else {
            float4 e4 = __ldg((const float4*)(nf + (size_t)dst * NFW)); // dst quad 0
#pragma unroll
            for (int u = 0; u < 4; u++) {
                float4 f = v[u];
                float4 n;
                n.x = __shfl_sync(FULL, v[u].x, lane + 1);
                n.y = __shfl_sync(FULL, v[u].y, lane + 1);
                n.z = __shfl_sync(FULL, v[u].z, lane + 1);
                n.w = __shfl_sync(FULL, v[u].w, lane + 1);
                float4 f0;
                if (u < 3) {
                    f0.x = __shfl_sync(FULL, v[(u+1)&3].x, 0);
                    f0.y = __shfl_sync(FULL, v[(u+1)&3].y, 0);
                    f0.z = __shfl_sync(FULL, v[(u+1)&3].z, 0);
                    f0.w = __shfl_sync(FULL, v[(u+1)&3].w, 0);
                } else {
                    f0 = e4;
                }
                if (lane == 31) n = f0;

                float4 o;
                if      (a == 1) o = make_float4(f.y, f.z, f.w, n.x);
                else if (a == 2) o = make_float4(f.z, f.w, n.x, n.y);
                else             o = make_float4(f.w, n.x, n.y, n.z);
                o.x *= m; o.y *= m; o.z *= m; o.w *= m;
                __stcs(ea4 + lane + 32*u, o);
            }
        }
        // head: cols 0..4 <- g_head; cols 5..5+a-1 <- src[0..a)
        if (lane < 5)
            __stcs(out + B + lane, g_head[e*5 + lane]);
        else if (lane < 5 + a)
            __stcs(out + B + lane, __ldg(nf + (size_t)i * NFW + (lane - 5)) * m);
    } else {
        const float4* rd4 = (const float4*)(nf + (size_t)dst * NFW);
        float4 v[4];
#pragma unroll
        for (int u = 0; u < 4; u++) v[u] = __ldg(rd4 + lane + 32*u);

        if (a == 0) {
#pragma unroll
            for (int u = 0; u < 4; u++) {
                float4 f = v[u];
                f.x *= m; f.y *= m; f.z *= m; f.w *= m;
                __stcs(ea4 + lane + 32*(u+4), f);
            }
        } else {
#pragma unroll
            for (int u = 0; u < 4; u++) {
                float4 f = v[u];
                float4 n;
                n.x = __shfl_sync(FULL, v[u].x, lane + 1);
                n.y = __shfl_sync(FULL, v[u].y, lane + 1);
                n.z = __shfl_sync(FULL, v[u].z, lane + 1);
                n.w = __shfl_sync(FULL, v[u].w, lane + 1);
                float4 f0;
                f0.x = __shfl_sync(FULL, v[(u+1)&3].x, 0);
                f0.y = __shfl_sync(FULL, v[(u+1)&3].y, 0);
                f0.z = __shfl_sync(FULL, v[(u+1)&3].z, 0);
                f0.w = __shfl_sync(FULL, v[(u+1)&3].w, 0);
                if (lane == 31) n = f0;

                float4 o;
                if      (a == 1) o = make_float4(f.y, f.z, f.w, n.x);
                else if (a == 2) o = make_float4(f.z, f.w, n.x, n.y);
                else             o = make_float4(f.w, n.x, n.y, n.z);

                int q = lane + 32*(u+4);
                if (q < 255) {
                    o.x *= m; o.y *= m; o.z *= m; o.w *= m;
                    __stcs(ea4 + q, o);
                }
            }
            // tail: cols 1025+a..1028 <- dst[508+a..512)
            int t = 4 - a;
            if (lane < t)
                __stcs(out + B + 1025 + a + lane,
                       __ldg(nf + (size_t)dst * NFW + 508 + a + lane) * m);
        }
    }
}

// ---------------------------------------------------------------------------
extern "C" void kernel_launch(void* const* d_in, const int* in_sizes, int n_in,
                              void* d_out, int out_size)
{
    const float* reid = (const float*)d_in[0];
    const float* pos  = (const float*)d_in[1];
    float* out = (float*)d_out;

    k_mega<<<1025, 256>>>(reid, pos, out);
    k_edge<<<NKE/4, 256>>>(out);
}